// round 10
// baseline (speedup 1.0000x reference)
#include <cuda_runtime.h>
#include <cuda_bf16.h>
#include <math.h>

// ---------------------------------------------------------------------------
// SelfAttention_39676907883685 — HMMA bf16 split-3
// CTA 128x128, 4 warps of 64x64 (high smem reuse), 128 threads,
// 2-stage cp.async double buffer, 2 CTAs/SM (launch_bounds(128,2)).
//
// C[m,n] = alpha * sum_k A[m,k]*B[n,k] (+bias); fp32 operands split into
// bf16 hi/lo; product = Ah*Bh + Ah*Bl + Al*Bh.
//
// Fusions:
//   GEMM1 epilogue emits split(v) for cols >= 2048          (MODE 1)
//   GEMM4 epilogue emits permuted split(q) directly         (MODE 2)
//   softmax fused with split(a)
// ---------------------------------------------------------------------------

typedef unsigned short u16;
typedef unsigned int   u32;

#define BK 32
#define ROWB 80                 // padded smem row bytes -> conflict-free ldsm
#define ARR (128 * ROWB)        // 10240 B
#define STAGE (4 * ARR)         // Ah, Al, Bh, Bl = 40960 B
#define SMEM_TOTAL (2 * STAGE)  // 81920 B ; x2 CTAs = 160KB <= 228KB

// ------------------------------ scratch ------------------------------------
__device__ float g_kv[(size_t)8192 * 4096];
__device__ float g_s [(size_t)4 * 2048 * 2048];

__device__ u16 g_xh [(size_t)8192 * 2048], g_xl [(size_t)8192 * 2048];
__device__ u16 g_wqh[(size_t)4096 * 2048], g_wql[(size_t)4096 * 2048];
__device__ u16 g_k0h[(size_t)4 * 2048 * 2048], g_k0l[(size_t)4 * 2048 * 2048];
__device__ u16 g_vh [(size_t)4 * 2048 * 2048], g_vl [(size_t)4 * 2048 * 2048];
__device__ u16 g_vth[(size_t)4 * 2048 * 2048], g_vtl[(size_t)4 * 2048 * 2048];
__device__ u16 g_ah [(size_t)4 * 2048 * 2048], g_al [(size_t)4 * 2048 * 2048];
__device__ u16 g_qph[(size_t)4 * 2048 * 2048], g_qpl[(size_t)4 * 2048 * 2048];
__device__ u16 g_wdh[(size_t)2048 * 2048], g_wdl[(size_t)2048 * 2048];

// ------------------------------ helpers ------------------------------------
__device__ __forceinline__ void split1(float x, u16& h, u16& l) {
    __nv_bfloat16 bh = __float2bfloat16_rn(x);
    h = __bfloat16_as_ushort(bh);
    float resid = x - __bfloat162float(bh);
    l = __bfloat16_as_ushort(__float2bfloat16_rn(resid));
}

__device__ __forceinline__ void pack_split2(float a, float b, u32& hi, u32& lo) {
    u16 h0, l0, h1, l1;
    split1(a, h0, l0);
    split1(b, h1, l1);
    hi = (u32)h0 | ((u32)h1 << 16);
    lo = (u32)l0 | ((u32)l1 << 16);
}

__device__ __forceinline__ void cp16(u32 saddr, const void* gptr) {
    asm volatile("cp.async.cg.shared.global [%0], [%1], 16;\n"
                 :: "r"(saddr), "l"(gptr));
}

__device__ __forceinline__ void ldsm4(u32* r, u32 addr) {
    asm volatile("ldmatrix.sync.aligned.m8n8.x4.shared.b16 {%0,%1,%2,%3}, [%4];\n"
                 : "=r"(r[0]), "=r"(r[1]), "=r"(r[2]), "=r"(r[3]) : "r"(addr));
}

__device__ __forceinline__ void mma16816(float* c, const u32* a, const u32* b) {
    asm volatile(
        "mma.sync.aligned.m16n8k16.row.col.f32.bf16.bf16.f32 "
        "{%0,%1,%2,%3}, {%4,%5,%6,%7}, {%8,%9}, {%0,%1,%2,%3};\n"
        : "+f"(c[0]), "+f"(c[1]), "+f"(c[2]), "+f"(c[3])
        : "r"(a[0]), "r"(a[1]), "r"(a[2]), "r"(a[3]), "r"(b[0]), "r"(b[1]));
}

// ------------------------- conversion kernels ------------------------------
__global__ __launch_bounds__(256) void split2d_kernel(
    const float* __restrict__ in, size_t ldin,
    u16* __restrict__ hi, u16* __restrict__ lo, int cols)
{
    size_t idx = (size_t)blockIdx.x * 256 + threadIdx.x;
    int cq = cols >> 2;
    size_t r  = idx / cq;
    size_t c4 = (idx % cq) * 4;
    float4 v = *(const float4*)(in + r * ldin + c4);
    u32 h01, l01, h23, l23;
    pack_split2(v.x, v.y, h01, l01);
    pack_split2(v.z, v.w, h23, l23);
    *(uint2*)(hi + r * cols + c4) = make_uint2(h01, h23);
    *(uint2*)(lo + r * cols + c4) = make_uint2(l01, l23);
}

__global__ __launch_bounds__(256) void transpose_split_kernel(
    const float* __restrict__ in, size_t ldin,
    u16* __restrict__ hi, u16* __restrict__ lo)
{
    __shared__ float t[32][33];
    const float* inb = in + (size_t)blockIdx.z * 2048 * ldin;
    size_t ob = (size_t)blockIdx.z * 2048 * 2048;
    int x0 = blockIdx.x * 32, y0 = blockIdx.y * 32;
    int tx = threadIdx.x, ty = threadIdx.y;
#pragma unroll
    for (int j = 0; j < 32; j += 8)
        t[ty + j][tx] = inb[(size_t)(y0 + ty + j) * ldin + x0 + tx];
    __syncthreads();
#pragma unroll
    for (int j = 0; j < 32; j += 8) {
        float v = t[tx][ty + j];
        u16 h, l;
        split1(v, h, l);
        size_t o = ob + (size_t)(x0 + ty + j) * 2048 + y0 + tx;
        hi[o] = h;
        lo[o] = l;
    }
}

// fused softmax + split(a): reads s, writes ah/al
__global__ __launch_bounds__(256) void softmax_split_kernel(
    const float* __restrict__ s, u16* __restrict__ ah, u16* __restrict__ al)
{
    const size_t row = blockIdx.x;
    const float* p = s + row * 2048;
    const int tid = threadIdx.x;

    float v[8];
    float mx = -1e30f;
#pragma unroll
    for (int j = 0; j < 8; j++) {
        v[j] = p[tid + j * 256];
        mx = fmaxf(mx, v[j]);
    }
    __shared__ float red[256];
    red[tid] = mx;
    __syncthreads();
#pragma unroll
    for (int st = 128; st > 0; st >>= 1) {
        if (tid < st) red[tid] = fmaxf(red[tid], red[tid + st]);
        __syncthreads();
    }
    mx = red[0];
    __syncthreads();

    float sum = 0.0f;
#pragma unroll
    for (int j = 0; j < 8; j++) {
        v[j] = __expf(v[j] - mx);
        sum += v[j];
    }
    red[tid] = sum;
    __syncthreads();
#pragma unroll
    for (int st = 128; st > 0; st >>= 1) {
        if (tid < st) red[tid] += red[tid + st];
        __syncthreads();
    }
    const float inv = 1.0f / red[0];
#pragma unroll
    for (int j = 0; j < 8; j++) {
        float a = v[j] * inv;
        u16 h, l;
        split1(a, h, l);
        ah[row * 2048 + tid + j * 256] = h;
        al[row * 2048 + tid + j * 256] = l;
    }
}

// ----------------------------- GEMM kernel ---------------------------------
// 128 threads, 4 warps in 2x2 grid, each computes 64x64.
// MODE 0: C = alpha*acc (+bias)
// MODE 1: C = acc; tiles with col >= 2048 also split -> oh/ol[row*2048+col-2048]
// MODE 2: no fp32 out; permuted split -> oh/ol[((rr&127)*64+z*16+(rr>>7))*2048+col]
template <int MODE>
__global__ __launch_bounds__(128, 2) void mma_gemm(
    const u16* __restrict__ Ah, const u16* __restrict__ Al,
    const u16* __restrict__ Bh, const u16* __restrict__ Bl,
    float* __restrict__ C, u16* __restrict__ oh, u16* __restrict__ ol,
    int M, int N, int K,
    size_t bA, size_t bB, size_t bC,
    float alpha, const float* __restrict__ bias)
{
    extern __shared__ char smem[];
    const u32 sbase = (u32)__cvta_generic_to_shared(smem);
    const int tid = threadIdx.x, lane = tid & 31, warp = tid >> 5;
    const int wm = warp & 1, wn = warp >> 1;     // 2 x 2 warps, 64 x 64 each
    const int z = blockIdx.z;
    Ah += (size_t)z * bA; Al += (size_t)z * bA;
    Bh += (size_t)z * bB; Bl += (size_t)z * bB;
    C  += (size_t)z * bC;
    const int m0 = blockIdx.y * 128, n0 = blockIdx.x * 128;

    float acc[4][8][4];
#pragma unroll
    for (int i = 0; i < 4; i++)
#pragma unroll
        for (int j = 0; j < 8; j++)
#pragma unroll
            for (int k = 0; k < 4; k++) acc[i][j][k] = 0.0f;

    const u32 a_off = (u32)((lane & 15) * ROWB + (lane >> 4) * 16);
    const u32 b_off = (u32)(((lane & 7) + ((lane >> 4) << 3)) * ROWB +
                            ((lane >> 3) & 1) * 16);

    const int nk = K / BK;

    // 512 16B-chunks per array, 128 threads -> 4 chunks/thread/array
    auto fill = [&](int buf, int kt) {
        u32 sb = sbase + buf * STAGE;
        int k0 = kt * BK;
#pragma unroll
        for (int j = 0; j < 4; j++) {
            int cc = tid * 4 + j;          // consecutive qq per thread
            int rr = cc >> 2, qq = cc & 3;
            size_t ga = (size_t)(m0 + rr) * K + k0 + qq * 8;
            size_t gb = (size_t)(n0 + rr) * K + k0 + qq * 8;
            u32 so = (u32)(rr * ROWB + qq * 16);
            cp16(sb + 0 * ARR + so, Ah + ga);
            cp16(sb + 1 * ARR + so, Al + ga);
            cp16(sb + 2 * ARR + so, Bh + gb);
            cp16(sb + 3 * ARR + so, Bl + gb);
        }
        asm volatile("cp.async.commit_group;\n" ::);
    };

    fill(0, 0);

    for (int kt = 0; kt < nk; kt++) {
        asm volatile("cp.async.wait_group 0;\n" ::);
        __syncthreads();
        if (kt + 1 < nk) fill((kt + 1) & 1, kt + 1);

        u32 sb = sbase + (kt & 1) * STAGE;
#pragma unroll
        for (int ks = 0; ks < 2; ks++) {
            u32 bh[4][4], bl[4][4];
#pragma unroll
            for (int np = 0; np < 4; np++) {
                u32 addr = sb + 2 * ARR +
                           (u32)((wn * 64 + np * 16) * ROWB + ks * 32) + b_off;
                ldsm4(bh[np], addr);
                ldsm4(bl[np], addr + ARR);
            }
#pragma unroll
            for (int mi = 0; mi < 4; mi++) {
                u32 ah[4], al[4];
                u32 addr = sb + (u32)((wm * 64 + mi * 16) * ROWB + ks * 32) + a_off;
                ldsm4(ah, addr);
                ldsm4(al, addr + ARR);
#pragma unroll
                for (int ni = 0; ni < 8; ni++)
                    mma16816(acc[mi][ni], ah, &bh[ni >> 1][(ni & 1) * 2]);
#pragma unroll
                for (int ni = 0; ni < 8; ni++)
                    mma16816(acc[mi][ni], ah, &bl[ni >> 1][(ni & 1) * 2]);
#pragma unroll
                for (int ni = 0; ni < 8; ni++)
                    mma16816(acc[mi][ni], al, &bh[ni >> 1][(ni & 1) * 2]);
            }
        }
        __syncthreads();
    }

    // ---- epilogue ----
#pragma unroll
    for (int mi = 0; mi < 4; mi++) {
        int row0 = m0 + wm * 64 + mi * 16 + (lane >> 2);
#pragma unroll
        for (int ni = 0; ni < 8; ni++) {
            int col = n0 + wn * 64 + ni * 8 + (lane & 3) * 2;
            float c00 = acc[mi][ni][0] * alpha, c01 = acc[mi][ni][1] * alpha;
            float c10 = acc[mi][ni][2] * alpha, c11 = acc[mi][ni][3] * alpha;

            if (MODE == 0) {
                if (bias) {
                    float b0 = bias[col], b1 = bias[col + 1];
                    c00 += b0; c01 += b1; c10 += b0; c11 += b1;
                }
                *(float2*)(C + (size_t)row0 * N + col) = make_float2(c00, c01);
                *(float2*)(C + (size_t)(row0 + 8) * N + col) = make_float2(c10, c11);
            } else if (MODE == 1) {
                *(float2*)(C + (size_t)row0 * N + col) = make_float2(c00, c01);
                *(float2*)(C + (size_t)(row0 + 8) * N + col) = make_float2(c10, c11);
                if (col >= 2048) {
                    int vc = col - 2048;
                    u32 h0, l0, h1, l1;
                    pack_split2(c00, c01, h0, l0);
                    pack_split2(c10, c11, h1, l1);
                    *(u32*)(oh + (size_t)row0 * 2048 + vc) = h0;
                    *(u32*)(ol + (size_t)row0 * 2048 + vc) = l0;
                    *(u32*)(oh + (size_t)(row0 + 8) * 2048 + vc) = h1;
                    *(u32*)(ol + (size_t)(row0 + 8) * 2048 + vc) = l1;
                }
            } else {  // MODE 2
                int r0 = row0, r1 = row0 + 8;
                int p0 = (r0 & 127) * 64 + z * 16 + (r0 >> 7);
                int p1 = (r1 & 127) * 64 + z * 16 + (r1 >> 7);
                u32 h0, l0, h1, l1;
                pack_split2(c00, c01, h0, l0);
                pack_split2(c10, c11, h1, l1);
                *(u32*)(oh + (size_t)p0 * 2048 + col) = h0;
                *(u32*)(ol + (size_t)p0 * 2048 + col) = l0;
                *(u32*)(oh + (size_t)p1 * 2048 + col) = h1;
                *(u32*)(ol + (size_t)p1 * 2048 + col) = l1;
            }
        }
    }
}

// ------------------------------- launch ------------------------------------
extern "C" void kernel_launch(void* const* d_in, const int* in_sizes, int n_in,
                              void* d_out, int out_size)
{
    const float* x       = (const float*)d_in[0];
    const float* w_qk    = (const float*)d_in[1];
    const float* w_dense = (const float*)d_in[2];
    const float* b_dense = (const float*)d_in[3];
    float* out = (float*)d_out;

    float *kv, *s;
    u16 *xh, *xl, *wqh, *wql, *k0h, *k0l, *vh, *vl, *vth, *vtl;
    u16 *ah, *al, *qph, *qpl, *wdh, *wdl;
    cudaGetSymbolAddress((void**)&kv,  g_kv);
    cudaGetSymbolAddress((void**)&s,   g_s);
    cudaGetSymbolAddress((void**)&xh,  g_xh);  cudaGetSymbolAddress((void**)&xl,  g_xl);
    cudaGetSymbolAddress((void**)&wqh, g_wqh); cudaGetSymbolAddress((void**)&wql, g_wql);
    cudaGetSymbolAddress((void**)&k0h, g_k0h); cudaGetSymbolAddress((void**)&k0l, g_k0l);
    cudaGetSymbolAddress((void**)&vh,  g_vh);  cudaGetSymbolAddress((void**)&vl,  g_vl);
    cudaGetSymbolAddress((void**)&vth, g_vth); cudaGetSymbolAddress((void**)&vtl, g_vtl);
    cudaGetSymbolAddress((void**)&ah,  g_ah);  cudaGetSymbolAddress((void**)&al,  g_al);
    cudaGetSymbolAddress((void**)&qph, g_qph); cudaGetSymbolAddress((void**)&qpl, g_qpl);
    cudaGetSymbolAddress((void**)&wdh, g_wdh); cudaGetSymbolAddress((void**)&wdl, g_wdl);

    cudaFuncSetAttribute(mma_gemm<0>, cudaFuncAttributeMaxDynamicSharedMemorySize,
                         SMEM_TOTAL);
    cudaFuncSetAttribute(mma_gemm<1>, cudaFuncAttributeMaxDynamicSharedMemorySize,
                         SMEM_TOTAL);
    cudaFuncSetAttribute(mma_gemm<2>, cudaFuncAttributeMaxDynamicSharedMemorySize,
                         SMEM_TOTAL);

    const size_t BATCH = (size_t)2048 * 2048;
    const float scale = 1.0f / sqrtf((float)((double)2048 * 2047 / 2.0));

    // split inputs
    split2d_kernel<<<16384, 256>>>(x,       2048, xh,  xl,  2048);
    split2d_kernel<<< 8192, 256>>>(w_qk,    2048, wqh, wql, 2048);
    split2d_kernel<<< 4096, 256>>>(w_dense, 2048, wdh, wdl, 2048);

    // 1) kv = x @ w_qk^T ; epilogue also emits split(v) for cols >= 2048
    mma_gemm<1><<<dim3(32, 64, 1), 128, SMEM_TOTAL>>>(
        xh, xl, wqh, wql, kv, vh, vl, 8192, 4096, 2048, 0, 0, 0, 1.0f, nullptr);

    // transposed splits (k0^T and v^T)
    transpose_split_kernel<<<dim3(64, 64, 4), dim3(32, 8)>>>(kv,        4096, k0h, k0l);
    transpose_split_kernel<<<dim3(64, 64, 4), dim3(32, 8)>>>(kv + 2048, 4096, vth, vtl);

    // 2) s = scale * k0t @ v^T  (batched)
    mma_gemm<0><<<dim3(16, 16, 4), 128, SMEM_TOTAL>>>(
        k0h, k0l, vh, vl, s, nullptr, nullptr,
        2048, 2048, 2048, BATCH, BATCH, BATCH, scale, nullptr);

    // 3) fused softmax + split(a)
    softmax_split_kernel<<<8192, 256>>>(s, ah, al);

    // 4) q = a @ vT^T ; epilogue emits permuted split(q) directly
    mma_gemm<2><<<dim3(16, 16, 4), 128, SMEM_TOTAL>>>(
        ah, al, vth, vtl, nullptr, qph, qpl,
        2048, 2048, 2048, BATCH, BATCH, 0, 1.0f, nullptr);

    // 5) out = qp @ w_dense^T + bias
    mma_gemm<0><<<dim3(16, 64, 1), 128, SMEM_TOTAL>>>(
        qph, qpl, wdh, wdl, out, nullptr, nullptr,
        8192, 2048, 2048, 0, 0, 0, 1.0f, b_dense);
}

// round 11
// speedup vs baseline: 1.6558x; 1.6558x over previous
#include <cuda_runtime.h>
#include <cuda_fp16.h>
#include <math.h>

// ---------------------------------------------------------------------------
// SelfAttention_39676907883685 — HMMA fp16 asymmetric split-2
//
// C[m,n] = alpha * sum_k A[m,k]*B[n,k] (+bias)
// A split into fp16 hi/lo (Ah + Al, ~22-bit effective), B single fp16.
// Product = Ah*B + Al*B  (2 MMAs per tile-step; error ~B-quant 2^-12).
//
// CTA tile 128x128, 8 warps of 64x32, BK=32, 2-stage cp.async (round-3
// config — empirically fastest across R3/R5/R6/R9/R10).
//
// Fusions:
//   GEMM1 epilogue emits fp16(v) for cols >= 2048            (MODE 1)
//   GEMM4 epilogue emits permuted fp16 split-2 of q          (MODE 2)
//   softmax fused with fp16 split-2 of a
// ---------------------------------------------------------------------------

typedef unsigned short u16;
typedef unsigned int   u32;

#define BK 32
#define ROWB 80                 // padded smem row bytes -> conflict-free ldsm
#define ARR (128 * ROWB)        // 10240 B
#define STAGE (3 * ARR)         // Ah, Al, B = 30720 B
#define SMEM_TOTAL (2 * STAGE)  // 61440 B

// ------------------------------ scratch ------------------------------------
__device__ float g_kv[(size_t)8192 * 4096];
__device__ float g_s [(size_t)4 * 2048 * 2048];

__device__ u16 g_xh [(size_t)8192 * 2048], g_xl [(size_t)8192 * 2048];
__device__ u16 g_wqh[(size_t)4096 * 2048];
__device__ u16 g_k0h[(size_t)4 * 2048 * 2048], g_k0l[(size_t)4 * 2048 * 2048];
__device__ u16 g_vh [(size_t)4 * 2048 * 2048];
__device__ u16 g_vth[(size_t)4 * 2048 * 2048];
__device__ u16 g_ah [(size_t)4 * 2048 * 2048], g_al [(size_t)4 * 2048 * 2048];
__device__ u16 g_qph[(size_t)4 * 2048 * 2048], g_qpl[(size_t)4 * 2048 * 2048];
__device__ u16 g_wdh[(size_t)2048 * 2048];

// ------------------------------ helpers ------------------------------------
__device__ __forceinline__ void split1h(float x, u16& h, u16& l) {
    __half hh = __float2half_rn(x);
    h = __half_as_ushort(hh);
    float resid = x - __half2float(hh);
    l = __half_as_ushort(__float2half_rn(resid));
}

__device__ __forceinline__ u16 f2h(float x) {
    return __half_as_ushort(__float2half_rn(x));
}

__device__ __forceinline__ u32 packh2(float a, float b) {
    return (u32)f2h(a) | ((u32)f2h(b) << 16);
}

__device__ __forceinline__ void pack_split2h(float a, float b, u32& hi, u32& lo) {
    u16 h0, l0, h1, l1;
    split1h(a, h0, l0);
    split1h(b, h1, l1);
    hi = (u32)h0 | ((u32)h1 << 16);
    lo = (u32)l0 | ((u32)l1 << 16);
}

__device__ __forceinline__ void cp16(u32 saddr, const void* gptr) {
    asm volatile("cp.async.cg.shared.global [%0], [%1], 16;\n"
                 :: "r"(saddr), "l"(gptr));
}

__device__ __forceinline__ void ldsm4(u32* r, u32 addr) {
    asm volatile("ldmatrix.sync.aligned.m8n8.x4.shared.b16 {%0,%1,%2,%3}, [%4];\n"
                 : "=r"(r[0]), "=r"(r[1]), "=r"(r[2]), "=r"(r[3]) : "r"(addr));
}

__device__ __forceinline__ void mma16816(float* c, const u32* a, const u32* b) {
    asm volatile(
        "mma.sync.aligned.m16n8k16.row.col.f32.f16.f16.f32 "
        "{%0,%1,%2,%3}, {%4,%5,%6,%7}, {%8,%9}, {%0,%1,%2,%3};\n"
        : "+f"(c[0]), "+f"(c[1]), "+f"(c[2]), "+f"(c[3])
        : "r"(a[0]), "r"(a[1]), "r"(a[2]), "r"(a[3]), "r"(b[0]), "r"(b[1]));
}

// ------------------------- conversion kernels ------------------------------
// fp16 split-2 of a dense region (A operands)
__global__ __launch_bounds__(256) void split2_kernel(
    const float* __restrict__ in, size_t ldin,
    u16* __restrict__ hi, u16* __restrict__ lo, int cols)
{
    size_t idx = (size_t)blockIdx.x * 256 + threadIdx.x;
    int cq = cols >> 2;
    size_t r  = idx / cq;
    size_t c4 = (idx % cq) * 4;
    float4 v = *(const float4*)(in + r * ldin + c4);
    u32 h01, l01, h23, l23;
    pack_split2h(v.x, v.y, h01, l01);
    pack_split2h(v.z, v.w, h23, l23);
    *(uint2*)(hi + r * cols + c4) = make_uint2(h01, h23);
    *(uint2*)(lo + r * cols + c4) = make_uint2(l01, l23);
}

// single fp16 quantization (B operands)
__global__ __launch_bounds__(256) void quant1_kernel(
    const float* __restrict__ in, size_t ldin,
    u16* __restrict__ hi, int cols)
{
    size_t idx = (size_t)blockIdx.x * 256 + threadIdx.x;
    int cq = cols >> 2;
    size_t r  = idx / cq;
    size_t c4 = (idx % cq) * 4;
    float4 v = *(const float4*)(in + r * ldin + c4);
    *(uint2*)(hi + r * cols + c4) =
        make_uint2(packh2(v.x, v.y), packh2(v.z, v.w));
}

// per-batch 2048x2048 transpose + fp16 split-2 (k0^T: A operand of GEMM2)
__global__ __launch_bounds__(256) void transpose_split2_kernel(
    const float* __restrict__ in, size_t ldin,
    u16* __restrict__ hi, u16* __restrict__ lo)
{
    __shared__ float t[32][33];
    const float* inb = in + (size_t)blockIdx.z * 2048 * ldin;
    size_t ob = (size_t)blockIdx.z * 2048 * 2048;
    int x0 = blockIdx.x * 32, y0 = blockIdx.y * 32;
    int tx = threadIdx.x, ty = threadIdx.y;
#pragma unroll
    for (int j = 0; j < 32; j += 8)
        t[ty + j][tx] = inb[(size_t)(y0 + ty + j) * ldin + x0 + tx];
    __syncthreads();
#pragma unroll
    for (int j = 0; j < 32; j += 8) {
        float v = t[tx][ty + j];
        u16 h, l;
        split1h(v, h, l);
        size_t o = ob + (size_t)(x0 + ty + j) * 2048 + y0 + tx;
        hi[o] = h;
        lo[o] = l;
    }
}

// per-batch transpose + single fp16 (v^T: B operand of GEMM4)
__global__ __launch_bounds__(256) void transpose_quant1_kernel(
    const float* __restrict__ in, size_t ldin, u16* __restrict__ hi)
{
    __shared__ float t[32][33];
    const float* inb = in + (size_t)blockIdx.z * 2048 * ldin;
    size_t ob = (size_t)blockIdx.z * 2048 * 2048;
    int x0 = blockIdx.x * 32, y0 = blockIdx.y * 32;
    int tx = threadIdx.x, ty = threadIdx.y;
#pragma unroll
    for (int j = 0; j < 32; j += 8)
        t[ty + j][tx] = inb[(size_t)(y0 + ty + j) * ldin + x0 + tx];
    __syncthreads();
#pragma unroll
    for (int j = 0; j < 32; j += 8) {
        size_t o = ob + (size_t)(x0 + ty + j) * 2048 + y0 + tx;
        hi[o] = f2h(t[tx][ty + j]);
    }
}

// fused softmax + fp16 split-2 of a (A operand of GEMM4)
__global__ __launch_bounds__(256) void softmax_split_kernel(
    const float* __restrict__ s, u16* __restrict__ ah, u16* __restrict__ al)
{
    const size_t row = blockIdx.x;
    const float* p = s + row * 2048;
    const int tid = threadIdx.x;

    float v[8];
    float mx = -1e30f;
#pragma unroll
    for (int j = 0; j < 8; j++) {
        v[j] = p[tid + j * 256];
        mx = fmaxf(mx, v[j]);
    }
    __shared__ float red[256];
    red[tid] = mx;
    __syncthreads();
#pragma unroll
    for (int st = 128; st > 0; st >>= 1) {
        if (tid < st) red[tid] = fmaxf(red[tid], red[tid + st]);
        __syncthreads();
    }
    mx = red[0];
    __syncthreads();

    float sum = 0.0f;
#pragma unroll
    for (int j = 0; j < 8; j++) {
        v[j] = __expf(v[j] - mx);
        sum += v[j];
    }
    red[tid] = sum;
    __syncthreads();
#pragma unroll
    for (int st = 128; st > 0; st >>= 1) {
        if (tid < st) red[tid] += red[tid + st];
        __syncthreads();
    }
    const float inv = 1.0f / red[0];
#pragma unroll
    for (int j = 0; j < 8; j++) {
        float a = v[j] * inv;
        u16 h, l;
        split1h(a, h, l);
        ah[row * 2048 + tid + j * 256] = h;
        al[row * 2048 + tid + j * 256] = l;
    }
}

// ----------------------------- GEMM kernel ---------------------------------
// A = Ah + Al (fp16 split-2), B single fp16.  D = Ah*B + Al*B.
// MODE 0: C = alpha*acc (+bias)
// MODE 1: C = acc; cols >= 2048 also emit fp16 -> oh[row*2048 + col-2048]
// MODE 2: no fp32 out; permuted fp16 split-2 -> oh/ol[perm(row)*2048+col]
template <int MODE>
__global__ __launch_bounds__(256) void mma_gemm(
    const u16* __restrict__ Ah, const u16* __restrict__ Al,
    const u16* __restrict__ B,
    float* __restrict__ C, u16* __restrict__ oh, u16* __restrict__ ol,
    int M, int N, int K,
    size_t bA, size_t bB, size_t bC,
    float alpha, const float* __restrict__ bias)
{
    extern __shared__ char smem[];
    const u32 sbase = (u32)__cvta_generic_to_shared(smem);
    const int tid = threadIdx.x, lane = tid & 31, warp = tid >> 5;
    const int wm = warp & 1, wn = warp >> 1;     // 2 x 4 warps, 64 x 32 each
    const int z = blockIdx.z;
    Ah += (size_t)z * bA; Al += (size_t)z * bA;
    B  += (size_t)z * bB;
    C  += (size_t)z * bC;
    const int m0 = blockIdx.y * 128, n0 = blockIdx.x * 128;

    float acc[4][4][4];
#pragma unroll
    for (int i = 0; i < 4; i++)
#pragma unroll
        for (int j = 0; j < 4; j++)
#pragma unroll
            for (int k = 0; k < 4; k++) acc[i][j][k] = 0.0f;

    const u32 a_off = (u32)((lane & 15) * ROWB + (lane >> 4) * 16);
    const u32 b_off = (u32)(((lane & 7) + ((lane >> 4) << 3)) * ROWB +
                            ((lane >> 3) & 1) * 16);

    const int nk = K / BK;

    auto fill = [&](int buf, int kt) {
        u32 sb = sbase + buf * STAGE;
        int k0 = kt * BK;
#pragma unroll
        for (int j = 0; j < 2; j++) {
            int cc = tid * 2 + j;
            int rr = cc >> 2, qq = cc & 3;
            size_t ga = (size_t)(m0 + rr) * K + k0 + qq * 8;
            size_t gb = (size_t)(n0 + rr) * K + k0 + qq * 8;
            u32 so = (u32)(rr * ROWB + qq * 16);
            cp16(sb + 0 * ARR + so, Ah + ga);
            cp16(sb + 1 * ARR + so, Al + ga);
            cp16(sb + 2 * ARR + so, B + gb);
        }
        asm volatile("cp.async.commit_group;\n" ::);
    };

    fill(0, 0);

    for (int kt = 0; kt < nk; kt++) {
        asm volatile("cp.async.wait_group 0;\n" ::);
        __syncthreads();
        if (kt + 1 < nk) fill((kt + 1) & 1, kt + 1);

        u32 sb = sbase + (kt & 1) * STAGE;
#pragma unroll
        for (int ks = 0; ks < 2; ks++) {
            u32 bf[2][4];
#pragma unroll
            for (int np = 0; np < 2; np++) {
                u32 addr = sb + 2 * ARR +
                           (u32)((wn * 32 + np * 16) * ROWB + ks * 32) + b_off;
                ldsm4(bf[np], addr);
            }
#pragma unroll
            for (int mi = 0; mi < 4; mi++) {
                u32 ah[4], al[4];
                u32 addr = sb + (u32)((wm * 64 + mi * 16) * ROWB + ks * 32) + a_off;
                ldsm4(ah, addr);
                ldsm4(al, addr + ARR);
#pragma unroll
                for (int ni = 0; ni < 4; ni++)
                    mma16816(acc[mi][ni], ah, &bf[ni >> 1][(ni & 1) * 2]);
#pragma unroll
                for (int ni = 0; ni < 4; ni++)
                    mma16816(acc[mi][ni], al, &bf[ni >> 1][(ni & 1) * 2]);
            }
        }
        __syncthreads();
    }

    // ---- epilogue ----
#pragma unroll
    for (int mi = 0; mi < 4; mi++) {
        int row0 = m0 + wm * 64 + mi * 16 + (lane >> 2);
#pragma unroll
        for (int ni = 0; ni < 4; ni++) {
            int col = n0 + wn * 32 + ni * 8 + (lane & 3) * 2;
            float c00 = acc[mi][ni][0] * alpha, c01 = acc[mi][ni][1] * alpha;
            float c10 = acc[mi][ni][2] * alpha, c11 = acc[mi][ni][3] * alpha;

            if (MODE == 0) {
                if (bias) {
                    float b0 = bias[col], b1 = bias[col + 1];
                    c00 += b0; c01 += b1; c10 += b0; c11 += b1;
                }
                *(float2*)(C + (size_t)row0 * N + col) = make_float2(c00, c01);
                *(float2*)(C + (size_t)(row0 + 8) * N + col) = make_float2(c10, c11);
            } else if (MODE == 1) {
                *(float2*)(C + (size_t)row0 * N + col) = make_float2(c00, c01);
                *(float2*)(C + (size_t)(row0 + 8) * N + col) = make_float2(c10, c11);
                if (col >= 2048) {
                    int vc = col - 2048;
                    *(u32*)(oh + (size_t)row0 * 2048 + vc) = packh2(c00, c01);
                    *(u32*)(oh + (size_t)(row0 + 8) * 2048 + vc) = packh2(c10, c11);
                }
            } else {  // MODE 2: permuted fp16 split-2
                int r0 = row0, r1 = row0 + 8;
                int p0 = (r0 & 127) * 64 + z * 16 + (r0 >> 7);
                int p1 = (r1 & 127) * 64 + z * 16 + (r1 >> 7);
                u32 h0, l0, h1, l1;
                pack_split2h(c00, c01, h0, l0);
                pack_split2h(c10, c11, h1, l1);
                *(u32*)(oh + (size_t)p0 * 2048 + col) = h0;
                *(u32*)(ol + (size_t)p0 * 2048 + col) = l0;
                *(u32*)(oh + (size_t)p1 * 2048 + col) = h1;
                *(u32*)(ol + (size_t)p1 * 2048 + col) = l1;
            }
        }
    }
}

// ------------------------------- launch ------------------------------------
extern "C" void kernel_launch(void* const* d_in, const int* in_sizes, int n_in,
                              void* d_out, int out_size)
{
    const float* x       = (const float*)d_in[0];
    const float* w_qk    = (const float*)d_in[1];
    const float* w_dense = (const float*)d_in[2];
    const float* b_dense = (const float*)d_in[3];
    float* out = (float*)d_out;

    float *kv, *s;
    u16 *xh, *xl, *wqh, *k0h, *k0l, *vh, *vth;
    u16 *ah, *al, *qph, *qpl, *wdh;
    cudaGetSymbolAddress((void**)&kv,  g_kv);
    cudaGetSymbolAddress((void**)&s,   g_s);
    cudaGetSymbolAddress((void**)&xh,  g_xh);  cudaGetSymbolAddress((void**)&xl,  g_xl);
    cudaGetSymbolAddress((void**)&wqh, g_wqh);
    cudaGetSymbolAddress((void**)&k0h, g_k0h); cudaGetSymbolAddress((void**)&k0l, g_k0l);
    cudaGetSymbolAddress((void**)&vh,  g_vh);
    cudaGetSymbolAddress((void**)&vth, g_vth);
    cudaGetSymbolAddress((void**)&ah,  g_ah);  cudaGetSymbolAddress((void**)&al,  g_al);
    cudaGetSymbolAddress((void**)&qph, g_qph); cudaGetSymbolAddress((void**)&qpl, g_qpl);
    cudaGetSymbolAddress((void**)&wdh, g_wdh);

    cudaFuncSetAttribute(mma_gemm<0>, cudaFuncAttributeMaxDynamicSharedMemorySize,
                         SMEM_TOTAL);
    cudaFuncSetAttribute(mma_gemm<1>, cudaFuncAttributeMaxDynamicSharedMemorySize,
                         SMEM_TOTAL);
    cudaFuncSetAttribute(mma_gemm<2>, cudaFuncAttributeMaxDynamicSharedMemorySize,
                         SMEM_TOTAL);

    const size_t BATCH = (size_t)2048 * 2048;
    const float scale = 1.0f / sqrtf((float)((double)2048 * 2047 / 2.0));

    // input conversions
    split2_kernel<<<16384, 256>>>(x,       2048, xh, xl, 2048);   // A of GEMM1
    quant1_kernel<<< 8192, 256>>>(w_qk,    2048, wqh, 2048);      // B of GEMM1
    quant1_kernel<<< 4096, 256>>>(w_dense, 2048, wdh, 2048);      // B of GEMM5

    // 1) kv = x @ w_qk^T ; epilogue emits fp16(v) for cols >= 2048 (B of GEMM2)
    mma_gemm<1><<<dim3(32, 64, 1), 256, SMEM_TOTAL>>>(
        xh, xl, wqh, kv, vh, nullptr, 8192, 4096, 2048, 0, 0, 0, 1.0f, nullptr);

    // k0^T split-2 (A of GEMM2), v^T single (B of GEMM4)
    transpose_split2_kernel<<<dim3(64, 64, 4), dim3(32, 8)>>>(kv,        4096, k0h, k0l);
    transpose_quant1_kernel<<<dim3(64, 64, 4), dim3(32, 8)>>>(kv + 2048, 4096, vth);

    // 2) s = scale * k0t @ v^T  (batched)
    mma_gemm<0><<<dim3(16, 16, 4), 256, SMEM_TOTAL>>>(
        k0h, k0l, vh, s, nullptr, nullptr,
        2048, 2048, 2048, BATCH, BATCH, BATCH, scale, nullptr);

    // 3) fused softmax + fp16 split-2 of a
    softmax_split_kernel<<<8192, 256>>>(s, ah, al);

    // 4) q = a @ vT^T ; epilogue emits permuted fp16 split-2 of q
    mma_gemm<2><<<dim3(16, 16, 4), 256, SMEM_TOTAL>>>(
        ah, al, vth, nullptr, qph, qpl,
        2048, 2048, 2048, BATCH, BATCH, 0, 1.0f, nullptr);

    // 5) out = qp @ w_dense^T + bias
    mma_gemm<0><<<dim3(16, 64, 1), 256, SMEM_TOTAL>>>(
        qph, qpl, wdh, out, nullptr, nullptr,
        8192, 2048, 2048, 0, 0, 0, 1.0f, b_dense);
}

// round 13
// speedup vs baseline: 1.9492x; 1.1772x over previous
#include <cuda_runtime.h>
#include <cuda_fp16.h>
#include <math.h>

// ---------------------------------------------------------------------------
// SelfAttention_39676907883685 — HMMA fp16, per-GEMM precision tuning
//
// C[m,n] = alpha * sum_k A[m,k]*B[n,k] (+bias), fp32 accumulate.
// SPLITA=2: A = Ah + Al (fp16 split-2, ~22-bit), 2 MMAs per step
// SPLITA=1: A single fp16, 1 MMA per step
// B always single fp16.
//
// Precision plan (error analysis per round-12 notes):
//   GEMM1 kv  = x(split2)   @ w_qk(fp16)    — error feeds everything
//   GEMM2 s   = k0t(fp16)   @ v(fp16)       — softmax damps: delta-a ~1e-5
//   GEMM4 q   = a(fp16)     @ vT(fp16)      — a in [6e-5,1]: rel err 2^-12
//   GEMM5 out = qp(split2)  @ w_dense(fp16) — un-damped, keep split-2
//
// CTA tile 128x128, 8 warps of 64x32, BK=32, 2-stage cp.async
// (empirically fastest config across R3/R5/R6/R9/R10).
//
// Fusions:
//   GEMM1 epilogue emits fp16(v) for cols >= 2048            (MODE 1)
//   GEMM4 epilogue emits permuted fp16 split-2 of q          (MODE 2)
//   softmax fused with fp16 quantization of a
// ---------------------------------------------------------------------------

typedef unsigned short u16;
typedef unsigned int   u32;

#define BK 32
#define ROWB 80                 // padded smem row bytes -> conflict-free ldsm
#define ARR (128 * ROWB)        // 10240 B per array

// ------------------------------ scratch ------------------------------------
__device__ float g_kv[(size_t)8192 * 4096];
__device__ float g_s [(size_t)4 * 2048 * 2048];

__device__ u16 g_xh [(size_t)8192 * 2048], g_xl [(size_t)8192 * 2048];
__device__ u16 g_wqh[(size_t)4096 * 2048];
__device__ u16 g_k0h[(size_t)4 * 2048 * 2048];
__device__ u16 g_vh [(size_t)4 * 2048 * 2048];
__device__ u16 g_vth[(size_t)4 * 2048 * 2048];
__device__ u16 g_ah [(size_t)4 * 2048 * 2048];
__device__ u16 g_qph[(size_t)4 * 2048 * 2048], g_qpl[(size_t)4 * 2048 * 2048];
__device__ u16 g_wdh[(size_t)2048 * 2048];

// ------------------------------ helpers ------------------------------------
__device__ __forceinline__ void split1h(float x, u16& h, u16& l) {
    __half hh = __float2half_rn(x);
    h = __half_as_ushort(hh);
    float resid = x - __half2float(hh);
    l = __half_as_ushort(__float2half_rn(resid));
}

__device__ __forceinline__ u16 f2h(float x) {
    return __half_as_ushort(__float2half_rn(x));
}

__device__ __forceinline__ u32 packh2(float a, float b) {
    return (u32)f2h(a) | ((u32)f2h(b) << 16);
}

__device__ __forceinline__ void pack_split2h(float a, float b, u32& hi, u32& lo) {
    u16 h0, l0, h1, l1;
    split1h(a, h0, l0);
    split1h(b, h1, l1);
    hi = (u32)h0 | ((u32)h1 << 16);
    lo = (u32)l0 | ((u32)l1 << 16);
}

__device__ __forceinline__ void cp16(u32 saddr, const void* gptr) {
    asm volatile("cp.async.cg.shared.global [%0], [%1], 16;\n"
                 :: "r"(saddr), "l"(gptr));
}

__device__ __forceinline__ void ldsm4(u32* r, u32 addr) {
    asm volatile("ldmatrix.sync.aligned.m8n8.x4.shared.b16 {%0,%1,%2,%3}, [%4];\n"
                 : "=r"(r[0]), "=r"(r[1]), "=r"(r[2]), "=r"(r[3]) : "r"(addr));
}

__device__ __forceinline__ void mma16816(float* c, const u32* a, const u32* b) {
    asm volatile(
        "mma.sync.aligned.m16n8k16.row.col.f32.f16.f16.f32 "
        "{%0,%1,%2,%3}, {%4,%5,%6,%7}, {%8,%9}, {%0,%1,%2,%3};\n"
        : "+f"(c[0]), "+f"(c[1]), "+f"(c[2]), "+f"(c[3])
        : "r"(a[0]), "r"(a[1]), "r"(a[2]), "r"(a[3]), "r"(b[0]), "r"(b[1]));
}

// ------------------------- conversion kernels ------------------------------
// fp16 split-2 of a dense region
__global__ __launch_bounds__(256) void split2_kernel(
    const float* __restrict__ in, size_t ldin,
    u16* __restrict__ hi, u16* __restrict__ lo, int cols)
{
    size_t idx = (size_t)blockIdx.x * 256 + threadIdx.x;
    int cq = cols >> 2;
    size_t r  = idx / cq;
    size_t c4 = (idx % cq) * 4;
    float4 v = *(const float4*)(in + r * ldin + c4);
    u32 h01, l01, h23, l23;
    pack_split2h(v.x, v.y, h01, l01);
    pack_split2h(v.z, v.w, h23, l23);
    *(uint2*)(hi + r * cols + c4) = make_uint2(h01, h23);
    *(uint2*)(lo + r * cols + c4) = make_uint2(l01, l23);
}

// single fp16 quantization
__global__ __launch_bounds__(256) void quant1_kernel(
    const float* __restrict__ in, size_t ldin,
    u16* __restrict__ hi, int cols)
{
    size_t idx = (size_t)blockIdx.x * 256 + threadIdx.x;
    int cq = cols >> 2;
    size_t r  = idx / cq;
    size_t c4 = (idx % cq) * 4;
    float4 v = *(const float4*)(in + r * ldin + c4);
    *(uint2*)(hi + r * cols + c4) =
        make_uint2(packh2(v.x, v.y), packh2(v.z, v.w));
}

// per-batch 2048x2048 transpose + single fp16
__global__ __launch_bounds__(256) void transpose_quant1_kernel(
    const float* __restrict__ in, size_t ldin, u16* __restrict__ hi)
{
    __shared__ float t[32][33];
    const float* inb = in + (size_t)blockIdx.z * 2048 * ldin;
    size_t ob = (size_t)blockIdx.z * 2048 * 2048;
    int x0 = blockIdx.x * 32, y0 = blockIdx.y * 32;
    int tx = threadIdx.x, ty = threadIdx.y;
#pragma unroll
    for (int j = 0; j < 32; j += 8)
        t[ty + j][tx] = inb[(size_t)(y0 + ty + j) * ldin + x0 + tx];
    __syncthreads();
#pragma unroll
    for (int j = 0; j < 32; j += 8) {
        size_t o = ob + (size_t)(x0 + ty + j) * 2048 + y0 + tx;
        hi[o] = f2h(t[tx][ty + j]);
    }
}

// fused softmax + single fp16 quantization of a
__global__ __launch_bounds__(256) void softmax_quant_kernel(
    const float* __restrict__ s, u16* __restrict__ ah)
{
    const size_t row = blockIdx.x;
    const float* p = s + row * 2048;
    const int tid = threadIdx.x;

    float v[8];
    float mx = -1e30f;
#pragma unroll
    for (int j = 0; j < 8; j++) {
        v[j] = p[tid + j * 256];
        mx = fmaxf(mx, v[j]);
    }
    __shared__ float red[256];
    red[tid] = mx;
    __syncthreads();
#pragma unroll
    for (int st = 128; st > 0; st >>= 1) {
        if (tid < st) red[tid] = fmaxf(red[tid], red[tid + st]);
        __syncthreads();
    }
    mx = red[0];
    __syncthreads();

    float sum = 0.0f;
#pragma unroll
    for (int j = 0; j < 8; j++) {
        v[j] = __expf(v[j] - mx);
        sum += v[j];
    }
    red[tid] = sum;
    __syncthreads();
#pragma unroll
    for (int st = 128; st > 0; st >>= 1) {
        if (tid < st) red[tid] += red[tid + st];
        __syncthreads();
    }
    const float inv = 1.0f / red[0];
#pragma unroll
    for (int j = 0; j < 8; j++)
        ah[row * 2048 + tid + j * 256] = f2h(v[j] * inv);
}

// ----------------------------- GEMM kernel ---------------------------------
// SPLITA=2: D = Ah*B + Al*B ; SPLITA=1: D = Ah*B
// MODE 0: C = alpha*acc (+bias)
// MODE 1: C = acc; cols >= 2048 also emit fp16 -> oh[row*2048 + col-2048]
// MODE 2: no fp32 out; permuted fp16 split-2 -> oh/ol[perm(row)*2048+col]
template <int MODE, int SPLITA>
__global__ __launch_bounds__(256) void mma_gemm(
    const u16* __restrict__ Ah, const u16* __restrict__ Al,
    const u16* __restrict__ B,
    float* __restrict__ C, u16* __restrict__ oh, u16* __restrict__ ol,
    int M, int N, int K,
    size_t bA, size_t bB, size_t bC,
    float alpha, const float* __restrict__ bias)
{
    constexpr u32 BOFF  = (u32)SPLITA * ARR;       // B array offset in stage
    constexpr u32 STAGEB = (u32)(SPLITA + 1) * ARR; // stage bytes

    extern __shared__ char smem[];
    const u32 sbase = (u32)__cvta_generic_to_shared(smem);
    const int tid = threadIdx.x, lane = tid & 31, warp = tid >> 5;
    const int wm = warp & 1, wn = warp >> 1;     // 2 x 4 warps, 64 x 32 each
    const int z = blockIdx.z;
    Ah += (size_t)z * bA;
    if (SPLITA == 2) Al += (size_t)z * bA;
    B  += (size_t)z * bB;
    C  += (size_t)z * bC;
    const int m0 = blockIdx.y * 128, n0 = blockIdx.x * 128;

    float acc[4][4][4];
#pragma unroll
    for (int i = 0; i < 4; i++)
#pragma unroll
        for (int j = 0; j < 4; j++)
#pragma unroll
            for (int k = 0; k < 4; k++) acc[i][j][k] = 0.0f;

    const u32 a_off = (u32)((lane & 15) * ROWB + (lane >> 4) * 16);
    const u32 b_off = (u32)(((lane & 7) + ((lane >> 4) << 3)) * ROWB +
                            ((lane >> 3) & 1) * 16);

    const int nk = K / BK;

    auto fill = [&](int buf, int kt) {
        u32 sb = sbase + buf * STAGEB;
        int k0 = kt * BK;
#pragma unroll
        for (int j = 0; j < 2; j++) {
            int cc = tid * 2 + j;
            int rr = cc >> 2, qq = cc & 3;
            size_t ga = (size_t)(m0 + rr) * K + k0 + qq * 8;
            size_t gb = (size_t)(n0 + rr) * K + k0 + qq * 8;
            u32 so = (u32)(rr * ROWB + qq * 16);
            cp16(sb + so, Ah + ga);
            if (SPLITA == 2) cp16(sb + ARR + so, Al + ga);
            cp16(sb + BOFF + so, B + gb);
        }
        asm volatile("cp.async.commit_group;\n" ::);
    };

    fill(0, 0);

    for (int kt = 0; kt < nk; kt++) {
        asm volatile("cp.async.wait_group 0;\n" ::);
        __syncthreads();
        if (kt + 1 < nk) fill((kt + 1) & 1, kt + 1);

        u32 sb = sbase + (kt & 1) * STAGEB;
#pragma unroll
        for (int ks = 0; ks < 2; ks++) {
            u32 bf[2][4];
#pragma unroll
            for (int np = 0; np < 2; np++) {
                u32 addr = sb + BOFF +
                           (u32)((wn * 32 + np * 16) * ROWB + ks * 32) + b_off;
                ldsm4(bf[np], addr);
            }
#pragma unroll
            for (int mi = 0; mi < 4; mi++) {
                u32 ah[4];
                u32 addr = sb + (u32)((wm * 64 + mi * 16) * ROWB + ks * 32) + a_off;
                ldsm4(ah, addr);
#pragma unroll
                for (int ni = 0; ni < 4; ni++)
                    mma16816(acc[mi][ni], ah, &bf[ni >> 1][(ni & 1) * 2]);
                if (SPLITA == 2) {
                    u32 al[4];
                    ldsm4(al, addr + ARR);
#pragma unroll
                    for (int ni = 0; ni < 4; ni++)
                        mma16816(acc[mi][ni], al, &bf[ni >> 1][(ni & 1) * 2]);
                }
            }
        }
        __syncthreads();
    }

    // ---- epilogue ----
#pragma unroll
    for (int mi = 0; mi < 4; mi++) {
        int row0 = m0 + wm * 64 + mi * 16 + (lane >> 2);
#pragma unroll
        for (int ni = 0; ni < 4; ni++) {
            int col = n0 + wn * 32 + ni * 8 + (lane & 3) * 2;
            float c00 = acc[mi][ni][0] * alpha, c01 = acc[mi][ni][1] * alpha;
            float c10 = acc[mi][ni][2] * alpha, c11 = acc[mi][ni][3] * alpha;

            if (MODE == 0) {
                if (bias) {
                    float b0 = bias[col], b1 = bias[col + 1];
                    c00 += b0; c01 += b1; c10 += b0; c11 += b1;
                }
                *(float2*)(C + (size_t)row0 * N + col) = make_float2(c00, c01);
                *(float2*)(C + (size_t)(row0 + 8) * N + col) = make_float2(c10, c11);
            } else if (MODE == 1) {
                *(float2*)(C + (size_t)row0 * N + col) = make_float2(c00, c01);
                *(float2*)(C + (size_t)(row0 + 8) * N + col) = make_float2(c10, c11);
                if (col >= 2048) {
                    int vc = col - 2048;
                    *(u32*)(oh + (size_t)row0 * 2048 + vc) = packh2(c00, c01);
                    *(u32*)(oh + (size_t)(row0 + 8) * 2048 + vc) = packh2(c10, c11);
                }
            } else {  // MODE 2: permuted fp16 split-2
                int r0 = row0, r1 = row0 + 8;
                int p0 = (r0 & 127) * 64 + z * 16 + (r0 >> 7);
                int p1 = (r1 & 127) * 64 + z * 16 + (r1 >> 7);
                u32 h0, l0, h1, l1;
                pack_split2h(c00, c01, h0, l0);
                pack_split2h(c10, c11, h1, l1);
                *(u32*)(oh + (size_t)p0 * 2048 + col) = h0;
                *(u32*)(ol + (size_t)p0 * 2048 + col) = l0;
                *(u32*)(oh + (size_t)p1 * 2048 + col) = h1;
                *(u32*)(ol + (size_t)p1 * 2048 + col) = l1;
            }
        }
    }
}

// ------------------------------- launch ------------------------------------
extern "C" void kernel_launch(void* const* d_in, const int* in_sizes, int n_in,
                              void* d_out, int out_size)
{
    const float* x       = (const float*)d_in[0];
    const float* w_qk    = (const float*)d_in[1];
    const float* w_dense = (const float*)d_in[2];
    const float* b_dense = (const float*)d_in[3];
    float* out = (float*)d_out;

    float *kv, *s;
    u16 *xh, *xl, *wqh, *k0h, *vh, *vth, *ah, *qph, *qpl, *wdh;
    cudaGetSymbolAddress((void**)&kv,  g_kv);
    cudaGetSymbolAddress((void**)&s,   g_s);
    cudaGetSymbolAddress((void**)&xh,  g_xh);  cudaGetSymbolAddress((void**)&xl,  g_xl);
    cudaGetSymbolAddress((void**)&wqh, g_wqh);
    cudaGetSymbolAddress((void**)&k0h, g_k0h);
    cudaGetSymbolAddress((void**)&vh,  g_vh);
    cudaGetSymbolAddress((void**)&vth, g_vth);
    cudaGetSymbolAddress((void**)&ah,  g_ah);
    cudaGetSymbolAddress((void**)&qph, g_qph); cudaGetSymbolAddress((void**)&qpl, g_qpl);
    cudaGetSymbolAddress((void**)&wdh, g_wdh);

    const int SM3 = 3 * ARR * 2;   // split-2 stage x2
    const int SM2 = 2 * ARR * 2;   // split-1 stage x2
    cudaFuncSetAttribute(mma_gemm<1, 2>, cudaFuncAttributeMaxDynamicSharedMemorySize, SM3);
    cudaFuncSetAttribute(mma_gemm<0, 1>, cudaFuncAttributeMaxDynamicSharedMemorySize, SM2);
    cudaFuncSetAttribute(mma_gemm<2, 1>, cudaFuncAttributeMaxDynamicSharedMemorySize, SM2);
    cudaFuncSetAttribute(mma_gemm<0, 2>, cudaFuncAttributeMaxDynamicSharedMemorySize, SM3);

    const size_t BATCH = (size_t)2048 * 2048;
    const float scale = 1.0f / sqrtf((float)((double)2048 * 2047 / 2.0));

    // input conversions
    split2_kernel<<<16384, 256>>>(x,       2048, xh, xl, 2048);   // A of GEMM1
    quant1_kernel<<< 8192, 256>>>(w_qk,    2048, wqh, 2048);      // B of GEMM1
    quant1_kernel<<< 4096, 256>>>(w_dense, 2048, wdh, 2048);      // B of GEMM5

    // 1) kv = x @ w_qk^T ; epilogue emits fp16(v) for cols >= 2048 (B of GEMM2)
    mma_gemm<1, 2><<<dim3(32, 64, 1), 256, SM3>>>(
        xh, xl, wqh, kv, vh, nullptr, 8192, 4096, 2048, 0, 0, 0, 1.0f, nullptr);

    // k0^T single (A of GEMM2), v^T single (B of GEMM4)
    transpose_quant1_kernel<<<dim3(64, 64, 4), dim3(32, 8)>>>(kv,        4096, k0h);
    transpose_quant1_kernel<<<dim3(64, 64, 4), dim3(32, 8)>>>(kv + 2048, 4096, vth);

    // 2) s = scale * k0t @ v^T  (batched, single-precision operands:
    //    softmax damps the quantization error to ~1e-5)
    mma_gemm<0, 1><<<dim3(16, 16, 4), 256, SM2>>>(
        k0h, nullptr, vh, s, nullptr, nullptr,
        2048, 2048, 2048, BATCH, BATCH, BATCH, scale, nullptr);

    // 3) fused softmax + fp16 quantization of a
    softmax_quant_kernel<<<8192, 256>>>(s, ah);

    // 4) q = a @ vT^T ; epilogue emits permuted fp16 split-2 of q
    mma_gemm<2, 1><<<dim3(16, 16, 4), 256, SM2>>>(
        ah, nullptr, vth, nullptr, qph, qpl,
        2048, 2048, 2048, BATCH, BATCH, 0, 1.0f, nullptr);

    // 5) out = qp @ w_dense^T + bias
    mma_gemm<0, 2><<<dim3(16, 64, 1), 256, SM3>>>(
        qph, qpl, wdh, out, nullptr, nullptr,
        8192, 2048, 2048, 0, 0, 0, 1.0f, b_dense);
}

// round 14
// speedup vs baseline: 2.7208x; 1.3958x over previous
#include <cuda_runtime.h>
#include <cuda_fp16.h>
#include <math.h>

// ---------------------------------------------------------------------------
// SelfAttention_39676907883685 — HMMA fp16 single-precision everywhere
//
// C[m,n] = alpha * sum_k A[m,k]*B[n,k] (+bias), fp32 accumulate,
// all operands single fp16 (error budget ~sqrt(5)*2^-12 ~ 5.4e-4 < 1e-3).
//
// GEMM plan (5 MMA units):
//   GEMM1 kv  = x @ w_qk^T       (2 units) -> fp16 k0u + fp16 v directly
//   GEMM2 s   = k0t @ v^T        (1 unit)  -> fp32 s
//   GEMM4 q   = a @ vT^T         (1 unit)  -> permuted fp16 qp
//   GEMM5 out = qp @ w_dense^T   (1 unit)  -> fp32 out + bias
//
// CTA tile 128x128, 8 warps of 64x32, BK=32, 2-stage cp.async
// (empirically fastest config across R3/R5/R6/R9/R10).
// No fp32 kv scratch: GEMM1 epilogue emits fp16; transposes are u16->u16.
// ---------------------------------------------------------------------------

typedef unsigned short u16;
typedef unsigned int   u32;

#define BK 32
#define ROWB 80                 // padded smem row bytes -> conflict-free ldsm
#define ARR (128 * ROWB)        // 10240 B per array
#define STAGE (2 * ARR)         // A, B = 20480 B
#define SMEM_TOTAL (2 * STAGE)  // 40960 B

// ------------------------------ scratch ------------------------------------
__device__ float g_s [(size_t)4 * 2048 * 2048];

__device__ u16 g_xh [(size_t)8192 * 2048];
__device__ u16 g_wqh[(size_t)4096 * 2048];
__device__ u16 g_wdh[(size_t)2048 * 2048];
__device__ u16 g_k0u[(size_t)4 * 2048 * 2048];   // k0 untransposed (fp16)
__device__ u16 g_vh [(size_t)4 * 2048 * 2048];   // v untransposed  (fp16)
__device__ u16 g_k0t[(size_t)4 * 2048 * 2048];   // k0^T (A of GEMM2)
__device__ u16 g_vth[(size_t)4 * 2048 * 2048];   // v^T  (B of GEMM4)
__device__ u16 g_ah [(size_t)4 * 2048 * 2048];   // softmax(a) fp16
__device__ u16 g_qph[(size_t)4 * 2048 * 2048];   // permuted q fp16

// ------------------------------ helpers ------------------------------------
__device__ __forceinline__ u16 f2h(float x) {
    return __half_as_ushort(__float2half_rn(x));
}
__device__ __forceinline__ u32 packh2(float a, float b) {
    return (u32)f2h(a) | ((u32)f2h(b) << 16);
}

__device__ __forceinline__ void cp16(u32 saddr, const void* gptr) {
    asm volatile("cp.async.cg.shared.global [%0], [%1], 16;\n"
                 :: "r"(saddr), "l"(gptr));
}

__device__ __forceinline__ void ldsm4(u32* r, u32 addr) {
    asm volatile("ldmatrix.sync.aligned.m8n8.x4.shared.b16 {%0,%1,%2,%3}, [%4];\n"
                 : "=r"(r[0]), "=r"(r[1]), "=r"(r[2]), "=r"(r[3]) : "r"(addr));
}

__device__ __forceinline__ void mma16816(float* c, const u32* a, const u32* b) {
    asm volatile(
        "mma.sync.aligned.m16n8k16.row.col.f32.f16.f16.f32 "
        "{%0,%1,%2,%3}, {%4,%5,%6,%7}, {%8,%9}, {%0,%1,%2,%3};\n"
        : "+f"(c[0]), "+f"(c[1]), "+f"(c[2]), "+f"(c[3])
        : "r"(a[0]), "r"(a[1]), "r"(a[2]), "r"(a[3]), "r"(b[0]), "r"(b[1]));
}

// ------------------------- conversion kernels ------------------------------
// single fp16 quantization of fp32 input
__global__ __launch_bounds__(256) void quant1_kernel(
    const float* __restrict__ in, size_t ldin,
    u16* __restrict__ hi, int cols)
{
    size_t idx = (size_t)blockIdx.x * 256 + threadIdx.x;
    int cq = cols >> 2;
    size_t r  = idx / cq;
    size_t c4 = (idx % cq) * 4;
    float4 v = *(const float4*)(in + r * ldin + c4);
    *(uint2*)(hi + r * cols + c4) =
        make_uint2(packh2(v.x, v.y), packh2(v.z, v.w));
}

// per-batch 2048x2048 u16 transpose: out[z][i][m] = in[z][m][i]
__global__ __launch_bounds__(256) void transpose16_kernel(
    const u16* __restrict__ in, u16* __restrict__ outp)
{
    __shared__ u16 t[32][34];
    size_t zb = (size_t)blockIdx.z * 2048 * 2048;
    const u16* inb = in + zb;
    u16* ob = outp + zb;
    int x0 = blockIdx.x * 32, y0 = blockIdx.y * 32;
    int tx = threadIdx.x, ty = threadIdx.y;   // 32 x 8
#pragma unroll
    for (int j = 0; j < 32; j += 8)
        t[ty + j][tx] = inb[(size_t)(y0 + ty + j) * 2048 + x0 + tx];
    __syncthreads();
#pragma unroll
    for (int j = 0; j < 32; j += 8)
        ob[(size_t)(x0 + ty + j) * 2048 + y0 + tx] = t[tx][ty + j];
}

// fused softmax + fp16 quantization of a
__global__ __launch_bounds__(256) void softmax_quant_kernel(
    const float* __restrict__ s, u16* __restrict__ ah)
{
    const size_t row = blockIdx.x;
    const float* p = s + row * 2048;
    const int tid = threadIdx.x;

    float v[8];
    float mx = -1e30f;
#pragma unroll
    for (int j = 0; j < 8; j++) {
        v[j] = p[tid + j * 256];
        mx = fmaxf(mx, v[j]);
    }
    __shared__ float red[256];
    red[tid] = mx;
    __syncthreads();
#pragma unroll
    for (int st = 128; st > 0; st >>= 1) {
        if (tid < st) red[tid] = fmaxf(red[tid], red[tid + st]);
        __syncthreads();
    }
    mx = red[0];
    __syncthreads();

    float sum = 0.0f;
#pragma unroll
    for (int j = 0; j < 8; j++) {
        v[j] = __expf(v[j] - mx);
        sum += v[j];
    }
    red[tid] = sum;
    __syncthreads();
#pragma unroll
    for (int st = 128; st > 0; st >>= 1) {
        if (tid < st) red[tid] += red[tid + st];
        __syncthreads();
    }
    const float inv = 1.0f / red[0];
#pragma unroll
    for (int j = 0; j < 8; j++)
        ah[row * 2048 + tid + j * 256] = f2h(v[j] * inv);
}

// ----------------------------- GEMM kernel ---------------------------------
// Single fp16 A and B, fp32 accumulate.
// MODE 0: C = alpha*acc + bias (fp32 out)
// MODE 1: fp16 out: col < 2048 -> o1[row*2048+col], else o2[row*2048+col-2048]
// MODE 2: permuted fp16 out -> o1[((rr&127)*64 + z*16 + (rr>>7))*2048 + col]
template <int MODE>
__global__ __launch_bounds__(256) void mma_gemm(
    const u16* __restrict__ A, const u16* __restrict__ B,
    float* __restrict__ C, u16* __restrict__ o1, u16* __restrict__ o2,
    int M, int N, int K,
    size_t bA, size_t bB, size_t bC,
    float alpha, const float* __restrict__ bias)
{
    extern __shared__ char smem[];
    const u32 sbase = (u32)__cvta_generic_to_shared(smem);
    const int tid = threadIdx.x, lane = tid & 31, warp = tid >> 5;
    const int wm = warp & 1, wn = warp >> 1;     // 2 x 4 warps, 64 x 32 each
    const int z = blockIdx.z;
    A += (size_t)z * bA;
    B += (size_t)z * bB;
    C += (size_t)z * bC;
    const int m0 = blockIdx.y * 128, n0 = blockIdx.x * 128;

    float acc[4][4][4];
#pragma unroll
    for (int i = 0; i < 4; i++)
#pragma unroll
        for (int j = 0; j < 4; j++)
#pragma unroll
            for (int k = 0; k < 4; k++) acc[i][j][k] = 0.0f;

    const u32 a_off = (u32)((lane & 15) * ROWB + (lane >> 4) * 16);
    const u32 b_off = (u32)(((lane & 7) + ((lane >> 4) << 3)) * ROWB +
                            ((lane >> 3) & 1) * 16);

    const int nk = K / BK;

    auto fill = [&](int buf, int kt) {
        u32 sb = sbase + buf * STAGE;
        int k0 = kt * BK;
#pragma unroll
        for (int j = 0; j < 2; j++) {
            int cc = tid * 2 + j;
            int rr = cc >> 2, qq = cc & 3;
            size_t ga = (size_t)(m0 + rr) * K + k0 + qq * 8;
            size_t gb = (size_t)(n0 + rr) * K + k0 + qq * 8;
            u32 so = (u32)(rr * ROWB + qq * 16);
            cp16(sb + so, A + ga);
            cp16(sb + ARR + so, B + gb);
        }
        asm volatile("cp.async.commit_group;\n" ::);
    };

    fill(0, 0);

    for (int kt = 0; kt < nk; kt++) {
        asm volatile("cp.async.wait_group 0;\n" ::);
        __syncthreads();
        if (kt + 1 < nk) fill((kt + 1) & 1, kt + 1);

        u32 sb = sbase + (kt & 1) * STAGE;
#pragma unroll
        for (int ks = 0; ks < 2; ks++) {
            u32 bf[2][4];
#pragma unroll
            for (int np = 0; np < 2; np++) {
                u32 addr = sb + ARR +
                           (u32)((wn * 32 + np * 16) * ROWB + ks * 32) + b_off;
                ldsm4(bf[np], addr);
            }
#pragma unroll
            for (int mi = 0; mi < 4; mi++) {
                u32 af[4];
                u32 addr = sb + (u32)((wm * 64 + mi * 16) * ROWB + ks * 32) + a_off;
                ldsm4(af, addr);
#pragma unroll
                for (int ni = 0; ni < 4; ni++)
                    mma16816(acc[mi][ni], af, &bf[ni >> 1][(ni & 1) * 2]);
            }
        }
        __syncthreads();
    }

    // ---- epilogue ----
#pragma unroll
    for (int mi = 0; mi < 4; mi++) {
        int row0 = m0 + wm * 64 + mi * 16 + (lane >> 2);
#pragma unroll
        for (int ni = 0; ni < 4; ni++) {
            int col = n0 + wn * 32 + ni * 8 + (lane & 3) * 2;
            float c00 = acc[mi][ni][0] * alpha, c01 = acc[mi][ni][1] * alpha;
            float c10 = acc[mi][ni][2] * alpha, c11 = acc[mi][ni][3] * alpha;

            if (MODE == 0) {
                if (bias) {
                    float b0 = bias[col], b1 = bias[col + 1];
                    c00 += b0; c01 += b1; c10 += b0; c11 += b1;
                }
                *(float2*)(C + (size_t)row0 * N + col) = make_float2(c00, c01);
                *(float2*)(C + (size_t)(row0 + 8) * N + col) = make_float2(c10, c11);
            } else if (MODE == 1) {
                // fp16-only output, split into k0 (col<2048) and v (col>=2048)
                u16* dst;
                int cc;
                if (col < 2048) { dst = o1; cc = col; }
                else            { dst = o2; cc = col - 2048; }
                *(u32*)(dst + (size_t)row0 * 2048 + cc) = packh2(c00, c01);
                *(u32*)(dst + (size_t)(row0 + 8) * 2048 + cc) = packh2(c10, c11);
            } else {  // MODE 2: permuted single fp16
                int r0 = row0, r1 = row0 + 8;
                int p0 = (r0 & 127) * 64 + z * 16 + (r0 >> 7);
                int p1 = (r1 & 127) * 64 + z * 16 + (r1 >> 7);
                *(u32*)(o1 + (size_t)p0 * 2048 + col) = packh2(c00, c01);
                *(u32*)(o1 + (size_t)p1 * 2048 + col) = packh2(c10, c11);
            }
        }
    }
}

// ------------------------------- launch ------------------------------------
extern "C" void kernel_launch(void* const* d_in, const int* in_sizes, int n_in,
                              void* d_out, int out_size)
{
    const float* x       = (const float*)d_in[0];
    const float* w_qk    = (const float*)d_in[1];
    const float* w_dense = (const float*)d_in[2];
    const float* b_dense = (const float*)d_in[3];
    float* out = (float*)d_out;

    float* s;
    u16 *xh, *wqh, *wdh, *k0u, *vh, *k0t, *vth, *ah, *qph;
    cudaGetSymbolAddress((void**)&s,   g_s);
    cudaGetSymbolAddress((void**)&xh,  g_xh);
    cudaGetSymbolAddress((void**)&wqh, g_wqh);
    cudaGetSymbolAddress((void**)&wdh, g_wdh);
    cudaGetSymbolAddress((void**)&k0u, g_k0u);
    cudaGetSymbolAddress((void**)&vh,  g_vh);
    cudaGetSymbolAddress((void**)&k0t, g_k0t);
    cudaGetSymbolAddress((void**)&vth, g_vth);
    cudaGetSymbolAddress((void**)&ah,  g_ah);
    cudaGetSymbolAddress((void**)&qph, g_qph);

    cudaFuncSetAttribute(mma_gemm<0>, cudaFuncAttributeMaxDynamicSharedMemorySize,
                         SMEM_TOTAL);
    cudaFuncSetAttribute(mma_gemm<1>, cudaFuncAttributeMaxDynamicSharedMemorySize,
                         SMEM_TOTAL);
    cudaFuncSetAttribute(mma_gemm<2>, cudaFuncAttributeMaxDynamicSharedMemorySize,
                         SMEM_TOTAL);

    const size_t BATCH = (size_t)2048 * 2048;
    const float scale = 1.0f / sqrtf((float)((double)2048 * 2047 / 2.0));

    // input quantization (all single fp16)
    quant1_kernel<<<16384, 256>>>(x,       2048, xh,  2048);
    quant1_kernel<<< 8192, 256>>>(w_qk,    2048, wqh, 2048);
    quant1_kernel<<< 4096, 256>>>(w_dense, 2048, wdh, 2048);

    // 1) kv = x @ w_qk^T ; epilogue emits fp16 k0u (cols<2048) + vh (cols>=2048)
    mma_gemm<1><<<dim3(32, 64, 1), 256, SMEM_TOTAL>>>(
        xh, wqh, nullptr, k0u, vh, 8192, 4096, 2048, 0, 0, 0, 1.0f, nullptr);

    // u16 transposes: k0u -> k0t (A of GEMM2), vh -> vth (B of GEMM4)
    transpose16_kernel<<<dim3(64, 64, 4), dim3(32, 8)>>>(k0u, k0t);
    transpose16_kernel<<<dim3(64, 64, 4), dim3(32, 8)>>>(vh,  vth);

    // 2) s = scale * k0t @ v^T  (batched)
    mma_gemm<0><<<dim3(16, 16, 4), 256, SMEM_TOTAL>>>(
        k0t, vh, s, nullptr, nullptr,
        2048, 2048, 2048, BATCH, BATCH, BATCH, scale, nullptr);

    // 3) fused softmax + fp16 quantization of a
    softmax_quant_kernel<<<8192, 256>>>(s, ah);

    // 4) q = a @ vT^T ; epilogue emits permuted fp16 q
    mma_gemm<2><<<dim3(16, 16, 4), 256, SMEM_TOTAL>>>(
        ah, vth, nullptr, qph, nullptr,
        2048, 2048, 2048, BATCH, BATCH, 0, 1.0f, nullptr);

    // 5) out = qp @ w_dense^T + bias
    mma_gemm<0><<<dim3(16, 64, 1), 256, SMEM_TOTAL>>>(
        qph, wdh, out, nullptr, nullptr,
        8192, 2048, 2048, 0, 0, 0, 1.0f, b_dense);
}